// round 4
// baseline (speedup 1.0000x reference)
#include <cuda_runtime.h>

// PSF patch renderer: B=128 images (512x512), S=1024 points per image.
// Grid = B blocks, 1024 threads each. Each block owns one image:
//   phase 1: zero the 1MB image (float4 stores)
//   phase 2: each thread renders one point's 6x6 ERF patch via atomicAdd.

#define NXC 512
#define NYC 512
#define PHW 3
#define PP  6          // patch size 2*PHW
#define BB  128
#define SS  1024

__global__ __launch_bounds__(1024, 1)
void psf_render_kernel(const float* __restrict__ z, float* __restrict__ out) {
    const int b   = blockIdx.x;
    const int tid = threadIdx.x;

    float* __restrict__ img = out + (size_t)b * (NXC * NYC);

    // ---- Phase 1: zero this block's image (512*512 = 262144 floats = 65536 float4) ----
    float4* img4 = reinterpret_cast<float4*>(img);
    const float4 z4 = make_float4(0.f, 0.f, 0.f, 0.f);
    #pragma unroll
    for (int i = 0; i < (NXC * NYC / 4) / 1024; i++) {   // 64 iterations
        img4[tid + i * 1024] = z4;
    }
    __syncthreads();

    // ---- Phase 2: render one point per thread ----
    // z layout: (B, 2, S) flattened: x at [b*2S + s], y at [b*2S + S + s]
    const float x0 = z[b * (2 * SS) + tid];
    const float y0 = z[b * (2 * SS) + SS + tid];

    // jnp.round = round-half-to-even = __float2int_rn
    const int px = __float2int_rn(x0) - PHW;
    const int py = __float2int_rn(y0) - PHW;

    const bool valid = (px >= 0) & (px < NXC - PP) & (py >= 0) & (py < NYC - PP);
    if (!valid) return;   // invalid patch contributes exactly zero

    const float x0p = x0 - (float)px;
    const float y0p = y0 - (float)py;

    // alpha = sqrt(2)*sigma, sigma=0.92
    const float inv_alpha = 1.0f / (1.41421356237309515f * 0.92f);

    // 7 boundary erfs per axis (boundaries at k-0.5, k=0..6), bins share edges.
    float ex[PP + 1], ey[PP + 1];
    #pragma unroll
    for (int k = 0; k <= PP; k++) {
        const float bk = (float)k - 0.5f;
        ex[k] = erff((bk - x0p) * inv_alpha);
        ey[k] = erff((bk - y0p) * inv_alpha);
    }

    // lx[k] = 0.5*(ex[k+1]-ex[k]); fold i0 = eta*N0*texp = 1000 into lx.
    float lx[PP], ly[PP];
    #pragma unroll
    for (int k = 0; k < PP; k++) {
        lx[k] = 500.0f * (ex[k + 1] - ex[k]);   // 1000 * 0.5
        ly[k] = 0.5f   * (ey[k + 1] - ey[k]);
    }

    // 6x6 scatter into this block's image. Uniform point positions -> low contention.
    #pragma unroll
    for (int i = 0; i < PP; i++) {
        float* row = img + (size_t)(px + i) * NYC + py;
        const float lxi = lx[i];
        #pragma unroll
        for (int j = 0; j < PP; j++) {
            atomicAdd(row + j, lxi * ly[j]);
        }
    }
}

extern "C" void kernel_launch(void* const* d_in, const int* in_sizes, int n_in,
                              void* d_out, int out_size) {
    const float* z = (const float*)d_in[0];
    float* out = (float*)d_out;
    psf_render_kernel<<<BB, 1024>>>(z, out);
}